// round 16
// baseline (speedup 1.0000x reference)
#include <cuda_runtime.h>
#include <cuda_fp16.h>
#include <cstdint>
#include <cstddef>

#define NSUP 65536
#define EDIM 512
#define CNUM 64
#define HNUM 8
#define LNUM 3
#define LN_EPS 1e-5f

// ---------------- static device scratch ----------------
__device__ __half g_Xh[NSUP * EDIM];
__device__ __half g_h[NSUP * EDIM];
__device__ float  g_feat[NSUP * EDIM];
__device__ __half g_W1t[LNUM * EDIM * EDIM];
__device__ __half g_W2t[LNUM * EDIM * EDIM];
__device__ float  g_WkT[EDIM * EDIM];
__device__ int    g_idx[NSUP];
__device__ int    g_cnti[CNUM];
__device__ int    g_off[CNUM + 1];
__device__ float  g_cnt[CNUM];
__device__ float  g_ctxp[CNUM * 8 * EDIM];
__device__ float  g_ctx[CNUM * EDIM];
__device__ float  g_q[CNUM * EDIM];
__device__ float  g_u[CNUM * HNUM * EDIM];
__device__ float  g_s[NSUP * HNUM];
__device__ float  g_attn[NSUP * HNUM];
__device__ float  g_mx[CNUM * HNUM];
__device__ float  g_sz[CNUM * HNUM];
__device__ float  g_wsp[CNUM * 8 * HNUM * EDIM];
__device__ float  g_ws[CNUM * HNUM * EDIM];
__device__ float  g_out[CNUM * EDIM];
__device__ float  g_coef[LNUM];

// ---------------- prep ----------------
__global__ void k_prep(const float* __restrict__ lw, const float* __restrict__ lt) {
    int tid = threadIdx.x;
    if (tid < CNUM) g_cnti[tid] = 0;
    if (tid == 0) {
        float m = fmaxf(lw[0], fmaxf(lw[1], lw[2]));
        float e0 = expf(lw[0] - m), e1 = expf(lw[1] - m), e2 = expf(lw[2] - m);
        float s = e0 + e1 + e2;
        g_coef[0] = e0 / s / lt[0];
        g_coef[1] = e1 / s / lt[1];
        g_coef[2] = e2 / s / lt[2];
    }
}

__global__ void k_convX(const float* __restrict__ X) {
    size_t i = ((size_t)blockIdx.x * 256 + threadIdx.x) * 8;
    float4 a = *(const float4*)(X + i);
    float4 b = *(const float4*)(X + i + 4);
    __half2* o = (__half2*)(g_Xh + i);
    o[0] = __floats2half2_rn(a.x, a.y);
    o[1] = __floats2half2_rn(a.z, a.w);
    o[2] = __floats2half2_rn(b.x, b.y);
    o[3] = __floats2half2_rn(b.z, b.w);
}

// z<3: W1[z]->g_W1t(fp16), z<6: W2[z-3]->g_W2t(fp16), z==6: Wk->g_WkT(fp32)
__global__ void k_transW(const float* __restrict__ W1, const float* __restrict__ W2,
                         const float* __restrict__ Wk) {
    __shared__ float t[32][33];
    int z = blockIdx.z;
    const float* src = (z < 3) ? (W1 + (size_t)z * EDIM * EDIM)
                     : (z < 6) ? (W2 + (size_t)(z - 3) * EDIM * EDIM)
                               : Wk;
    int x = blockIdx.x * 32 + threadIdx.x;
    int y = blockIdx.y * 32 + threadIdx.y;
    t[threadIdx.y][threadIdx.x] = src[(size_t)y * EDIM + x];
    __syncthreads();
    int orow = blockIdx.x * 32 + threadIdx.y;
    int ocol = blockIdx.y * 32 + threadIdx.x;
    float v = t[threadIdx.x][threadIdx.y];
    if (z < 3)      g_W1t[(size_t)z * EDIM * EDIM + (size_t)orow * EDIM + ocol] = __float2half_rn(v);
    else if (z < 6) g_W2t[(size_t)(z - 3) * EDIM * EDIM + (size_t)orow * EDIM + ocol] = __float2half_rn(v);
    else            g_WkT[(size_t)orow * EDIM + ocol] = v;
}

__global__ void k_hist(const int* __restrict__ labels) {
    __shared__ int hh[CNUM];
    int tid = threadIdx.x;
    if (tid < CNUM) hh[tid] = 0;
    __syncthreads();
    atomicAdd(&hh[labels[blockIdx.x * 256 + tid]], 1);
    __syncthreads();
    if (tid < CNUM) atomicAdd(&g_cnti[tid], hh[tid]);
}

__global__ void k_scan() {
    if (threadIdx.x == 0) {
        int s = 0;
        for (int c = 0; c < CNUM; c++) {
            g_off[c] = s;
            g_cnt[c] = (float)g_cnti[c];
            s += g_cnti[c];
        }
        g_off[CNUM] = s;
    }
}

// deterministic in-order scatter: one block per class
__global__ void k_scatter(const int* __restrict__ labels) {
    __shared__ int wsum[8];
    __shared__ int wbase[9];
    int c = blockIdx.x;
    int tid = threadIdx.x, lane = tid & 31, wid = tid >> 5;
    int base = g_off[c];
    for (int t0 = 0; t0 < NSUP; t0 += 256) {
        int i = t0 + tid;
        int flag = (labels[i] == c);
        unsigned mask = __ballot_sync(0xffffffffu, flag);
        int rank = __popc(mask & ((1u << lane) - 1u));
        if (lane == 0) wsum[wid] = __popc(mask);
        __syncthreads();
        if (tid == 0) {
            int s = 0;
            for (int w = 0; w < 8; w++) { wbase[w] = s; s += wsum[w]; }
            wbase[8] = s;
        }
        __syncthreads();
        if (flag) g_idx[base + wbase[wid] + rank] = i;
        base += wbase[8];
        __syncthreads();
    }
}

// ================= GEMM: C = A(MxK fp16) * Bt(NxK fp16)^T + bias =================
// mma.sync + ldmatrix + XOR-swizzled SMEM + 3-stage cp.async pipeline.
// Tile 128x128xK, BK=64, 8 warps (2x4), each warp 64x32 output.
#define BM 128
#define BN 128
#define BK 64
#define KT_N (EDIM / BK)            // 8
#define STG_A (BM * BK * 2)         // 16384 bytes
#define STG_B (BN * BK * 2)         // 16384 bytes
#define STG   (STG_A + STG_B)       // 32768
#define GEMM_SMEM (3 * STG)         // 98304

__device__ __forceinline__ uint32_t sm_u32(const void* p) {
    uint32_t a;
    asm("{ .reg .u64 t; cvta.to.shared.u64 t, %1; cvt.u32.u64 %0, t; }" : "=r"(a) : "l"(p));
    return a;
}
__device__ __forceinline__ void cp_async16(unsigned s, const void* g) {
    asm volatile("cp.async.cg.shared.global [%0], [%1], 16;\n" :: "r"(s), "l"(g));
}
__device__ __forceinline__ void cp_commit() { asm volatile("cp.async.commit_group;\n"); }
template <int W> __device__ __forceinline__ void cp_wait() {
    asm volatile("cp.async.wait_group %0;\n" :: "n"(W));
}
__device__ __forceinline__ void mma16816(float* c, const uint32_t* a, const uint32_t* b) {
    asm volatile(
        "mma.sync.aligned.m16n8k16.row.col.f32.f16.f16.f32 "
        "{%0,%1,%2,%3}, {%4,%5,%6,%7}, {%8,%9}, {%0,%1,%2,%3};\n"
        : "+f"(c[0]), "+f"(c[1]), "+f"(c[2]), "+f"(c[3])
        : "r"(a[0]), "r"(a[1]), "r"(a[2]), "r"(a[3]), "r"(b[0]), "r"(b[1]));
}
__device__ __forceinline__ void ldmx4(uint32_t& r0, uint32_t& r1, uint32_t& r2, uint32_t& r3,
                                      uint32_t addr) {
    asm volatile("ldmatrix.sync.aligned.m8n8.x4.shared.b16 {%0,%1,%2,%3}, [%4];"
                 : "=r"(r0), "=r"(r1), "=r"(r2), "=r"(r3) : "r"(addr));
}

__global__ void __launch_bounds__(256) k_gemm5(const __half* __restrict__ A,
                                               const __half* __restrict__ Bt,
                                               const float* __restrict__ bias,
                                               float* __restrict__ C) {
    extern __shared__ char smem[];
    uint32_t sb = sm_u32(smem);
    int tid = threadIdx.x, lane = tid & 31, warp = tid >> 5;
    int bm = blockIdx.x, bn = blockIdx.y;
    int wm = warp >> 2, wn = warp & 3;   // 2x4 warps, each 64x32

    const __half* gA = A + (size_t)bm * BM * EDIM;
    const __half* gB = Bt + (size_t)bn * BN * EDIM;

    // cp.async layout: 8 consecutive lanes cover one row's 8 chunks (16B each);
    // chunk c of row r stored at phys column (c ^ (r&7)) -> conflict-free both ways.
    int lr = tid >> 3, lc = tid & 7;   // base row (0..31), chunk (0..7)

    #define ISSUE(kt, st) do {                                                              \
        unsigned ba_ = sb + (st) * STG;                                                     \
        unsigned bb_ = ba_ + STG_A;                                                         \
        _Pragma("unroll")                                                                   \
        for (int rb_ = 0; rb_ < 4; rb_++) {                                                 \
            int r_ = lr + rb_ * 32;                                                         \
            uint32_t sw_ = (uint32_t)(r_ * 128 + ((lc ^ (r_ & 7)) << 4));                   \
            cp_async16(ba_ + sw_, gA + (size_t)r_ * EDIM + (kt) * BK + lc * 8);             \
            cp_async16(bb_ + sw_, gB + (size_t)r_ * EDIM + (kt) * BK + lc * 8);             \
        }                                                                                   \
        cp_commit();                                                                        \
    } while (0)

    ISSUE(0, 0);
    ISSUE(1, 1);
    ISSUE(2, 2);

    float acc[4][4][4];
    #pragma unroll
    for (int mi = 0; mi < 4; mi++)
        #pragma unroll
        for (int ni = 0; ni < 4; ni++) {
            acc[mi][ni][0] = 0.f; acc[mi][ni][1] = 0.f;
            acc[mi][ni][2] = 0.f; acc[mi][ni][3] = 0.f;
        }

    // ldmatrix per-lane addressing (precomputed row parts):
    // A, mtile mi: row = wm*64 + mi*16 + (lane&15); sel = lane>>4 (k 8-half)
    int arow = wm * 64 + (lane & 15);
    int asel = lane >> 4;
    uint32_t arb[4]; int ars[4];
    #pragma unroll
    for (int mi = 0; mi < 4; mi++) {
        int r = arow + mi * 16;
        arb[mi] = (uint32_t)(r * 128);
        ars[mi] = r & 7;
    }
    // B, pair pi covers ntiles 2pi,2pi+1: row = wn*32 + pi*16 + ((lane>>4)<<3) + (lane&7)
    // bsel = (lane>>3)&1 selects k 8-half
    int brow0 = wn * 32 + ((lane >> 4) << 3) + (lane & 7);
    int bsel = (lane >> 3) & 1;
    uint32_t brb[2]; int brs[2];
    #pragma unroll
    for (int pi = 0; pi < 2; pi++) {
        int r = brow0 + pi * 16;
        brb[pi] = (uint32_t)(r * 128);
        brs[pi] = r & 7;
    }

    for (int i = 0; i < KT_N; i++) {
        if (i < KT_N - 2) cp_wait<2>();
        else if (i == KT_N - 2) cp_wait<1>();
        else cp_wait<0>();
        __syncthreads();

        int st = i % 3;
        uint32_t ab = sb + st * STG;
        uint32_t bb = ab + STG_A;

        #pragma unroll
        for (int ks = 0; ks < 4; ks++) {
            uint32_t af[4][4], bf[4][2];
            int kh = 2 * ks;
            #pragma unroll
            for (int mi = 0; mi < 4; mi++) {
                uint32_t addr = ab + arb[mi] + (uint32_t)((((kh + asel) ^ ars[mi])) << 4);
                ldmx4(af[mi][0], af[mi][1], af[mi][2], af[mi][3], addr);
            }
            #pragma unroll
            for (int pi = 0; pi < 2; pi++) {
                uint32_t addr = bb + brb[pi] + (uint32_t)((((kh + bsel) ^ brs[pi])) << 4);
                ldmx4(bf[2 * pi][0], bf[2 * pi][1], bf[2 * pi + 1][0], bf[2 * pi + 1][1], addr);
            }
            #pragma unroll
            for (int mi = 0; mi < 4; mi++)
                #pragma unroll
                for (int ni = 0; ni < 4; ni++)
                    mma16816(acc[mi][ni], af[mi], bf[ni]);
        }
        __syncthreads();
        if (i + 3 < KT_N) ISSUE(i + 3, st);
    }

    int g = lane >> 2, tg = lane & 3;
    int rowB = bm * BM + wm * 64;
    int colB = bn * BN + wn * 32;
    #pragma unroll
    for (int mi = 0; mi < 4; mi++) {
        #pragma unroll
        for (int ni = 0; ni < 4; ni++) {
            int r = rowB + mi * 16 + g;
            int col = colB + ni * 8 + tg * 2;
            float b0 = bias[col], b1 = bias[col + 1];
            C[(size_t)r * EDIM + col]           = acc[mi][ni][0] + b0;
            C[(size_t)r * EDIM + col + 1]       = acc[mi][ni][1] + b1;
            C[(size_t)(r + 8) * EDIM + col]     = acc[mi][ni][2] + b0;
            C[(size_t)(r + 8) * EDIM + col + 1] = acc[mi][ni][3] + b1;
        }
    }
    #undef ISSUE
}

// ---------------- LayerNorm + ReLU -> fp16 (warp per row) ----------------
__global__ void k_lnrelu(const float* __restrict__ gamma, const float* __restrict__ beta) {
    int warp = threadIdx.x >> 5, lane = threadIdx.x & 31;
    size_t row = (size_t)blockIdx.x * 8 + warp;
    const float* x = g_feat + row * EDIM + lane * 16;
    float v[16];
    float s = 0.f, sq = 0.f;
    #pragma unroll
    for (int j = 0; j < 4; j++) {
        float4 f = *(const float4*)(x + j * 4);
        v[j*4+0] = f.x; v[j*4+1] = f.y; v[j*4+2] = f.z; v[j*4+3] = f.w;
        s += f.x + f.y + f.z + f.w;
        sq += f.x*f.x + f.y*f.y + f.z*f.z + f.w*f.w;
    }
    #pragma unroll
    for (int o = 16; o > 0; o >>= 1) {
        s  += __shfl_xor_sync(0xffffffffu, s, o);
        sq += __shfl_xor_sync(0xffffffffu, sq, o);
    }
    float mu = s * (1.f / EDIM);
    float var = sq * (1.f / EDIM) - mu * mu;
    float rs = rsqrtf(var + LN_EPS);
    const float* ga = gamma + lane * 16;
    const float* be = beta + lane * 16;
    __half2* o2 = (__half2*)(g_h + row * EDIM + lane * 16);
    #pragma unroll
    for (int j = 0; j < 8; j++) {
        float y0 = fmaxf((v[2*j]   - mu) * rs * ga[2*j]   + be[2*j],   0.f);
        float y1 = fmaxf((v[2*j+1] - mu) * rs * ga[2*j+1] + be[2*j+1], 0.f);
        o2[j] = __floats2half2_rn(y0, y1);
    }
}

// ---------------- class context (segment mean), deterministic 8-way ----------------
__global__ void k_ctxp() {
    int c = blockIdx.x, j = blockIdx.y, tid = threadIdx.x;
    int start = g_off[c], len = g_off[c + 1] - start;
    int ms = start + (len * j) / 8;
    int me = start + (len * (j + 1)) / 8;
    float a0 = 0.f, a1 = 0.f;
    for (int m = ms; m < me; m++) {
        int idx = g_idx[m];
        float2 f = *(const float2*)(g_feat + (size_t)idx * EDIM + 2 * tid);
        a0 += f.x; a1 += f.y;
    }
    g_ctxp[(size_t)(c * 8 + j) * EDIM + 2 * tid]     = a0;
    g_ctxp[(size_t)(c * 8 + j) * EDIM + 2 * tid + 1] = a1;
}

__global__ void k_ctxred() {
    int c = blockIdx.x, e = threadIdx.x;
    float s = 0.f;
    #pragma unroll
    for (int j = 0; j < 8; j++) s += g_ctxp[(size_t)(c * 8 + j) * EDIM + e];
    g_ctx[c * EDIM + e] = s / g_cnt[c];
}

// ---------------- q = ctx@Wq + bq ----------------
__global__ void k_q(const float* __restrict__ Wq, const float* __restrict__ bq) {
    __shared__ float cs[EDIM];
    int c = blockIdx.x, e = threadIdx.x;
    cs[e] = g_ctx[c * EDIM + e];
    __syncthreads();
    float acc = 0.f;
    for (int k = 0; k < EDIM; k++) acc += cs[k] * Wq[(size_t)k * EDIM + e];
    g_q[c * EDIM + e] = acc + bq[e];
}

// ---------------- u[c,h,e] = sum_d q[c,h,d] * Wk[e, h*64+d] ----------------
__global__ void k_u() {
    __shared__ float qs[64];
    int c = blockIdx.x, h = blockIdx.y, e = threadIdx.x;
    if (e < 64) qs[e] = g_q[c * EDIM + h * 64 + e];
    __syncthreads();
    float acc = 0.f;
    #pragma unroll 8
    for (int d = 0; d < 64; d++) acc += qs[d] * g_WkT[(size_t)(h * 64 + d) * EDIM + e];
    g_u[(size_t)(c * HNUM + h) * EDIM + e] = acc;
}

// ---------------- scores s[n,h] = scale * feat[n] . u[label[n],h] ----------------
__global__ void k_score(const int* __restrict__ labels) {
    int i = blockIdx.x * 256 + threadIdx.x;
    int n = i >> 3, h = i & 7;
    int lab = labels[n];
    const float4* f4 = (const float4*)(g_feat + (size_t)n * EDIM);
    const float4* u4 = (const float4*)(g_u + (size_t)(lab * HNUM + h) * EDIM);
    float acc = 0.f;
    #pragma unroll 4
    for (int k = 0; k < EDIM / 4; k++) {
        float4 f = f4[k], u = u4[k];
        acc += f.x * u.x + f.y * u.y + f.z * u.z + f.w * u.w;
    }
    g_s[i] = acc * 0.125f;  // 1/sqrt(64)
}

// ---------------- per (c,h): max & sumexp over members ----------------
__global__ void k_smax() {
    __shared__ float red[256];
    int b = blockIdx.x, c = b >> 3, h = b & 7, tid = threadIdx.x;
    int s0 = g_off[c], s1 = g_off[c + 1];
    float m = -1e30f;
    for (int i = s0 + tid; i < s1; i += 256) m = fmaxf(m, g_s[g_idx[i] * HNUM + h]);
    red[tid] = m;
    __syncthreads();
    #pragma unroll
    for (int o = 128; o > 0; o >>= 1) {
        if (tid < o) red[tid] = fmaxf(red[tid], red[tid + o]);
        __syncthreads();
    }
    float mx = red[0];
    __syncthreads();
    float sum = 0.f;
    for (int i = s0 + tid; i < s1; i += 256) sum += expf(g_s[g_idx[i] * HNUM + h] - mx);
    red[tid] = sum;
    __syncthreads();
    #pragma unroll
    for (int o = 128; o > 0; o >>= 1) {
        if (tid < o) red[tid] += red[tid + o];
        __syncthreads();
    }
    if (tid == 0) { g_mx[b] = mx; g_sz[b] = red[0]; }
}

__global__ void k_attn(const int* __restrict__ labels) {
    int i = blockIdx.x * 256 + threadIdx.x;
    int n = i >> 3, h = i & 7;
    int b = labels[n] * HNUM + h;
    g_attn[i] = expf(g_s[i] - g_mx[b]) / g_sz[b];
}

// ---------------- ws[c,h,e] = sum_{n in c} attn[n,h]*feat[n,e] ----------------
__global__ void k_wsump() {
    __shared__ float as[HNUM];
    int c = blockIdx.x, j = blockIdx.y, tid = threadIdx.x;
    int start = g_off[c], len = g_off[c + 1] - start;
    int ms = start + (len * j) / 8;
    int me = start + (len * (j + 1)) / 8;
    float acc[HNUM][2];
    #pragma unroll
    for (int h = 0; h < HNUM; h++) { acc[h][0] = 0.f; acc[h][1] = 0.f; }
    for (int m = ms; m < me; m++) {
        int idx = g_idx[m];
        if (tid < HNUM) as[tid] = g_attn[idx * HNUM + tid];
        __syncthreads();
        float2 f = *(const float2*)(g_feat + (size_t)idx * EDIM + 2 * tid);
        #pragma unroll
        for (int h = 0; h < HNUM; h++) {
            acc[h][0] += as[h] * f.x;
            acc[h][1] += as[h] * f.y;
        }
        __syncthreads();
    }
    #pragma unroll
    for (int h = 0; h < HNUM; h++) {
        size_t base = ((size_t)(c * 8 + j) * HNUM + h) * EDIM + 2 * tid;
        g_wsp[base]     = acc[h][0];
        g_wsp[base + 1] = acc[h][1];
    }
}

__global__ void k_wsred() {
    int b = blockIdx.x;        // c*8+h
    int c = b >> 3, h = b & 7, e = threadIdx.x;
    float s = 0.f;
    #pragma unroll
    for (int j = 0; j < 8; j++) s += g_wsp[((size_t)(c * 8 + j) * HNUM + h) * EDIM + e];
    g_ws[(size_t)b * EDIM + e] = s;
}

// ---------------- out[c,x] = ws[c, x/64, :] @ Wv[:, x] + bv[x] ----------------
__global__ void k_out(const float* __restrict__ Wv, const float* __restrict__ bv) {
    __shared__ float ws_s[HNUM * EDIM];
    int c = blockIdx.x, x = threadIdx.x;
    #pragma unroll
    for (int j = 0; j < 8; j++) ws_s[j * EDIM + x] = g_ws[(size_t)(c * HNUM) * EDIM + j * EDIM + x];
    __syncthreads();
    int h = x >> 6;
    float acc = 0.f;
    for (int e = 0; e < EDIM; e++) acc += ws_s[h * EDIM + e] * Wv[(size_t)e * EDIM + x];
    g_out[c * EDIM + x] = acc + bv[x];
}

// ---------------- proto = out@Wo + bo; final accumulate ----------------
__global__ void k_proto(const float* __restrict__ Wo, const float* __restrict__ bo,
                        int lvl, float* __restrict__ fin) {
    __shared__ float os[EDIM];
    int c = blockIdx.x, e = threadIdx.x;
    os[e] = g_out[c * EDIM + e];
    __syncthreads();
    float acc = 0.f;
    for (int k = 0; k < EDIM; k++) acc += os[k] * Wo[(size_t)k * EDIM + e];
    float v = (acc + bo[e]) * g_coef[lvl];
    if (lvl == 0) fin[c * EDIM + e] = v;
    else          fin[c * EDIM + e] += v;
}

// ---------------- launch ----------------
extern "C" void kernel_launch(void* const* d_in, const int* in_sizes, int n_in,
                              void* d_out, int out_size) {
    const float* X      = (const float*)d_in[0];
    const int*   labels = (const int*)d_in[1];
    const float* W1     = (const float*)d_in[2];
    const float* b1     = (const float*)d_in[3];
    const float* gamma  = (const float*)d_in[4];
    const float* beta   = (const float*)d_in[5];
    const float* W2     = (const float*)d_in[6];
    const float* b2     = (const float*)d_in[7];
    const float* Wq     = (const float*)d_in[8];
    const float* bq     = (const float*)d_in[9];
    const float* Wk     = (const float*)d_in[10];
    // d_in[11]=bk cancels in softmax
    const float* Wv     = (const float*)d_in[12];
    const float* bv     = (const float*)d_in[13];
    const float* Wo     = (const float*)d_in[14];
    const float* bo     = (const float*)d_in[15];
    const float* lw     = (const float*)d_in[16];
    const float* lt     = (const float*)d_in[17];
    float* fin = (float*)d_out;

    cudaFuncSetAttribute(k_gemm5, cudaFuncAttributeMaxDynamicSharedMemorySize, GEMM_SMEM);

    __half* pXh; cudaGetSymbolAddress((void**)&pXh, g_Xh);
    __half* ph;  cudaGetSymbolAddress((void**)&ph,  g_h);
    __half* pW1; cudaGetSymbolAddress((void**)&pW1, g_W1t);
    __half* pW2; cudaGetSymbolAddress((void**)&pW2, g_W2t);
    float*  pF;  cudaGetSymbolAddress((void**)&pF,  g_feat);

    k_prep<<<1, 64>>>(lw, lt);
    k_convX<<<(NSUP * EDIM / 8) / 256, 256>>>(X);
    k_transW<<<dim3(16, 16, 7), dim3(32, 32)>>>(W1, W2, Wk);
    k_hist<<<NSUP / 256, 256>>>(labels);
    k_scan<<<1, 32>>>();
    k_scatter<<<CNUM, 256>>>(labels);

    for (int l = 0; l < LNUM; l++) {
        k_gemm5<<<dim3(NSUP / BM, EDIM / BN), 256, GEMM_SMEM>>>(
            pXh, pW1 + (size_t)l * EDIM * EDIM, b1 + l * EDIM, pF);
        k_lnrelu<<<NSUP / 8, 256>>>(gamma + l * EDIM, beta + l * EDIM);
        k_gemm5<<<dim3(NSUP / BM, EDIM / BN), 256, GEMM_SMEM>>>(
            ph, pW2 + (size_t)l * EDIM * EDIM, b2 + l * EDIM, pF);
        k_ctxp<<<dim3(CNUM, 8), 256>>>();
        k_ctxred<<<CNUM, EDIM>>>();
        k_q<<<CNUM, EDIM>>>(Wq, bq);
        k_u<<<dim3(CNUM, HNUM), EDIM>>>();
        k_score<<<NSUP * HNUM / 256, 256>>>(labels);
        k_smax<<<CNUM * HNUM, 256>>>();
        k_attn<<<NSUP * HNUM / 256, 256>>>(labels);
        k_wsump<<<dim3(CNUM, 8), 256>>>();
        k_wsred<<<CNUM * HNUM, EDIM>>>();
        k_out<<<CNUM, EDIM>>>(Wv, bv);
        k_proto<<<CNUM, EDIM>>>(Wo, bo, l, fin);
    }
}